// round 17
// baseline (speedup 1.0000x reference)
#include <cuda_runtime.h>
#include <cstdint>

#define NUM_BINS 31
#define THREADS 256
#define WARPS 8
#define GRID_R 1184                 // reduce: 148 SMs * 8 blocks -> 1 wave
#define GRID_H 888                  // hist:   148 SMs * 6 blocks (proven cfg)
#define COPIES 8
#define ROWS (WARPS * COPIES)       // 64 int sub-histograms per block
#define ROWW (NUM_BINS + 2)         // 33-wide rows: slot 31 = mx bucket, 32 pad

// ---------------- device-global scratch ------------------------------------
__device__ float  g_pmn[GRID_R];
__device__ float  g_pmx[GRID_R];
__device__ double g_ps [GRID_R];
__device__ double g_pss[GRID_R];
__device__ int    g_pnz[GRID_R];
__device__ int    g_counts[32];     // slot 31 = val==mx bucket
__device__ unsigned int g_ticket;

// ---------------------------------------------------------------------------
// Pass 1: per-block min/max/sum/ss/nnz partials (round-8 exact; 37.8us).
__global__ void __launch_bounds__(THREADS, 8)
reduce_kernel(const float4* __restrict__ x4, int n4) {
    if (blockIdx.x == 0) {
        if (threadIdx.x < 32) g_counts[threadIdx.x] = 0;
        if (threadIdx.x == 32) g_ticket = 0u;
    }

    float mn =  __int_as_float(0x7F800000);
    float mx = -__int_as_float(0x7F800000);
    float s  = 0.f, ss = 0.f;
    int   nz = 0;

    const int T = GRID_R * THREADS;
    for (int i = blockIdx.x * THREADS + threadIdx.x; i < n4; i += T) {
        float4 a = x4[i];
        mn = fminf(mn, fminf(fminf(a.x, a.y), fminf(a.z, a.w)));
        mx = fmaxf(mx, fmaxf(fmaxf(a.x, a.y), fmaxf(a.z, a.w)));
        s += a.x; s += a.y; s += a.z; s += a.w;
        ss = fmaf(a.x, a.x, ss); ss = fmaf(a.y, a.y, ss);
        ss = fmaf(a.z, a.z, ss); ss = fmaf(a.w, a.w, ss);
        nz += (a.x != 0.f) + (a.y != 0.f) + (a.z != 0.f) + (a.w != 0.f);
    }

    #pragma unroll
    for (int o = 16; o > 0; o >>= 1) {
        mn = fminf(mn, __shfl_xor_sync(0xFFFFFFFFu, mn, o));
        mx = fmaxf(mx, __shfl_xor_sync(0xFFFFFFFFu, mx, o));
        s  += __shfl_xor_sync(0xFFFFFFFFu, s,  o);
        ss += __shfl_xor_sync(0xFFFFFFFFu, ss, o);
        nz += __shfl_xor_sync(0xFFFFFFFFu, nz, o);
    }

    __shared__ float  sh_mn[WARPS], sh_mx[WARPS];
    __shared__ double sh_s[WARPS],  sh_ss[WARPS];
    __shared__ int    sh_nz[WARPS];
    int lane = threadIdx.x & 31;
    int wid  = threadIdx.x >> 5;
    if (lane == 0) {
        sh_mn[wid] = mn; sh_mx[wid] = mx;
        sh_s[wid] = (double)s; sh_ss[wid] = (double)ss;
        sh_nz[wid] = nz;
    }
    __syncthreads();
    if (wid == 0) {
        mn = (lane < WARPS) ? sh_mn[lane] :  __int_as_float(0x7F800000);
        mx = (lane < WARPS) ? sh_mx[lane] : -__int_as_float(0x7F800000);
        double ds  = (lane < WARPS) ? sh_s[lane]  : 0.0;
        double dss = (lane < WARPS) ? sh_ss[lane] : 0.0;
        nz = (lane < WARPS) ? sh_nz[lane] : 0;
        #pragma unroll
        for (int o = 4; o > 0; o >>= 1) {
            mn = fminf(mn, __shfl_xor_sync(0xFFFFFFFFu, mn, o));
            mx = fmaxf(mx, __shfl_xor_sync(0xFFFFFFFFu, mx, o));
            ds  += __shfl_xor_sync(0xFFFFFFFFu, ds,  o);
            dss += __shfl_xor_sync(0xFFFFFFFFu, dss, o);
            nz  += __shfl_xor_sync(0xFFFFFFFFu, nz,  o);
        }
        if (lane == 0) {
            g_pmn[blockIdx.x] = mn;
            g_pmx[blockIdx.x] = mx;
            g_ps [blockIdx.x] = ds;
            g_pss[blockIdx.x] = dss;
            g_pnz[blockIdx.x] = nz;
        }
    }
}

// ---------------------------------------------------------------------------
// Pass 2: round-8 histogram + HOT-WINDOW register counting. The 4 bins
// [lo, lo+3] around the mean's bin (~50% of normal data) are counted in ONE
// packed u32 register (8-bit fields; flushed into the table mid-loop and at
// end, so merge logic is unchanged). Cold elements use a PREDICATED
// red.shared (no branch) into the proven 8-copy table. If the ATOMS unit
// charges per active lane, atomic time halves and hist goes DRAM-bound.
__global__ void __launch_bounds__(THREADS, 6)
hist_kernel(const float4* __restrict__ x4, int n4,
            float* __restrict__ out, int n) {
    __shared__ int s_hist[ROWS][ROWW];
    __shared__ float  sh_f[WARPS];
    __shared__ double sh_d0[WARPS];
    __shared__ float s_mn, s_mx;
    __shared__ int   s_lo;

    // --- reduce partial min/max/sum (partials are L2-resident) ---
    {
        float mn =  __int_as_float(0x7F800000);
        float mx = -__int_as_float(0x7F800000);
        double ds = 0.0;
        for (int i = threadIdx.x; i < GRID_R; i += THREADS) {
            mn = fminf(mn, g_pmn[i]);
            mx = fmaxf(mx, g_pmx[i]);
            ds += g_ps[i];
        }
        #pragma unroll
        for (int o = 16; o > 0; o >>= 1) {
            mn = fminf(mn, __shfl_xor_sync(0xFFFFFFFFu, mn, o));
            mx = fmaxf(mx, __shfl_xor_sync(0xFFFFFFFFu, mx, o));
            ds += __shfl_xor_sync(0xFFFFFFFFu, ds, o);
        }
        int lane = threadIdx.x & 31, wid = threadIdx.x >> 5;
        if (lane == 0) { sh_f[wid] = mn; sh_d0[wid] = ds; }
        __syncthreads();
        if (threadIdx.x == 0) {
            float m = sh_f[0];
            double d = sh_d0[0];
            #pragma unroll
            for (int w = 1; w < WARPS; w++) { m = fminf(m, sh_f[w]); d += sh_d0[w]; }
            s_mn = m;
            sh_d0[0] = d;
        }
        __syncthreads();
        if (lane == 0) sh_f[wid] = mx;
        __syncthreads();
        if (threadIdx.x == 0) {
            float m = sh_f[0];
            #pragma unroll
            for (int w = 1; w < WARPS; w++) m = fmaxf(m, sh_f[w]);
            s_mx = m;
            float inv0 = (float)NUM_BINS / (m - s_mn);
            float mean = (float)(sh_d0[0] / (double)n);
            int mm = (int)fmaf(mean, inv0, -s_mn * inv0);
            s_lo = min(max(mm - 1, 0), NUM_BINS - 4);   // window [lo, lo+3]
        }
        __syncthreads();
    }

    const float mn   = s_mn, mx = s_mx;
    const int   lo   = s_lo;
    const float step = (mx - mn) / (float)NUM_BINS;
    const float inv  = (float)NUM_BINS / (mx - mn);
    const float nb   = -mn * inv;   // bin coord = fmaf(val, inv, nb)

    for (int i = threadIdx.x; i < ROWS * ROWW; i += THREADS)
        ((int*)s_hist)[i] = 0;
    __syncthreads();

    const int T    = GRID_H * THREADS;
    const int gtid = blockIdx.x * THREADS + threadIdx.x;
    const int lane = threadIdx.x & 31;
    const int w    = threadIdx.x >> 5;
    int* const hrow = s_hist[(w << 3) | (lane & 7)];
    const unsigned hbase = (unsigned)__cvta_generic_to_shared(hrow);

    unsigned cnt = 0u;              // 4 x 8-bit window counters

    #define COUNT1(val) do {                                                  \
        int _idx = (int)fmaf((val), inv, nb);                                 \
        unsigned _d = (unsigned)(_idx - lo);                                  \
        cnt += (_d <= 3u) ? (1u << (_d << 3)) : 0u;                           \
        unsigned _a = hbase + ((unsigned)_idx << 2);                          \
        asm volatile("{\n\t.reg .pred p;\n\t"                                 \
                     "setp.gt.u32 p, %1, 3;\n\t"                              \
                     "@p red.shared.add.u32 [%0], %2;\n\t}"                   \
                     :: "r"(_a), "r"(_d), "r"(1) : "memory");                 \
    } while (0)

    #define P4(v) do { COUNT1((v).x); COUNT1((v).y); COUNT1((v).z); COUNT1((v).w); } while (0)

    #define FLUSH() do {                                                      \
        atomicAdd(&hrow[lo],     (int)( cnt        & 255u));                  \
        atomicAdd(&hrow[lo + 1], (int)((cnt >> 8)  & 255u));                  \
        atomicAdd(&hrow[lo + 2], (int)((cnt >> 16) & 255u));                  \
        atomicAdd(&hrow[lo + 3], (int)( cnt >> 24        ));                  \
        cnt = 0u; } while (0)

    const int nfull = n4 / T;       // full strips
    const int mid   = nfull >> 1;

    #pragma unroll 1
    for (int ph = 0; ph < 2; ph++) {
        int k0 = ph ? mid   : 0;
        int k1 = ph ? nfull : mid;
        int cstr = k1 - k0;
        int i = gtid + k0 * T;
        if (cstr >= 2) {
            float4 a = x4[i];
            float4 b = x4[i + T];
            i += 2 * T;
            int k = k0 + 2;
            for (; k + 1 < k1; k += 2) {
                float4 a2 = x4[i];        // next pair issues first
                float4 b2 = x4[i + T];
                i += 2 * T;
                P4(a); P4(b);
                a = a2; b = b2;
            }
            P4(a); P4(b);
            if (k < k1) {                 // odd strip count
                float4 c = x4[i];
                P4(c);
            }
        } else if (cstr == 1) {
            float4 c = x4[i];
            P4(c);
        }
        if (ph == 1) {                    // partial strip
            int ii = gtid + nfull * T;
            if (ii < n4) {
                float4 c = x4[ii];
                P4(c);
            }
        }
        FLUSH();                          // window counts -> table (safe <255)
    }
    __syncthreads();

    // merge table (32 columns incl. slot 31 mx bucket) to global
    if (threadIdx.x < 32) {
        int b = threadIdx.x;
        int t = 0;
        #pragma unroll
        for (int r = 0; r < ROWS; r++) t += s_hist[r][b];
        atomicAdd(&g_counts[b], t);
    }

    // --- last-block finalize ---
    __shared__ bool amLast;
    __threadfence();
    __syncthreads();
    if (threadIdx.x == 0)
        amLast = (atomicAdd(&g_ticket, 1u) == (unsigned)(GRID_H - 1));
    __syncthreads();
    if (!amLast) return;

    double ds = 0.0, dss = 0.0;
    long long nz = 0;
    for (int i2 = threadIdx.x; i2 < GRID_R; i2 += THREADS) {
        ds  += g_ps[i2];
        dss += g_pss[i2];
        nz  += g_pnz[i2];
    }
    #pragma unroll
    for (int o = 16; o > 0; o >>= 1) {
        ds  += __shfl_xor_sync(0xFFFFFFFFu, ds,  o);
        dss += __shfl_xor_sync(0xFFFFFFFFu, dss, o);
        nz  += __shfl_xor_sync(0xFFFFFFFFu, nz,  o);
    }
    __shared__ double sh_d[WARPS], sh_d2[WARPS];
    __shared__ long long sh_n[WARPS];
    int wid = threadIdx.x >> 5;
    if (lane == 0) { sh_d[wid] = ds; sh_d2[wid] = dss; sh_n[wid] = nz; }
    __syncthreads();
    if (threadIdx.x == 0) {
        double tds = 0.0, tdss = 0.0; long long tnz = 0;
        #pragma unroll
        for (int ww = 0; ww < WARPS; ww++) { tds += sh_d[ww]; tdss += sh_d2[ww]; tnz += sh_n[ww]; }
        out[0] = mn;
        out[1] = mx;
        out[2] = (float)n;
        out[3] = (float)tnz;
        out[4] = (float)tds;
        out[5] = (float)tdss;
    }
    if (threadIdx.x < NUM_BINS) {
        int cnt2 = g_counts[threadIdx.x];
        if (threadIdx.x == NUM_BINS - 1) cnt2 += g_counts[NUM_BINS]; // mx bucket
        out[6 + threadIdx.x] = (float)cnt2;
    }
    if (threadIdx.x <= NUM_BINS) {
        float e = __fadd_rn(mn, __fmul_rn((float)threadIdx.x, step));
        if (threadIdx.x == NUM_BINS) e = mx;
        out[6 + NUM_BINS + threadIdx.x] = e;
    }
}

// ---------------------------------------------------------------------------
extern "C" void kernel_launch(void* const* d_in, const int* in_sizes, int n_in,
                              void* d_out, int out_size) {
    const float* x = (const float*)d_in[0];
    int n  = in_sizes[0];
    int n4 = n / 4;
    float* out = (float*)d_out;

    reduce_kernel<<<GRID_R, THREADS>>>((const float4*)x, n4);
    hist_kernel  <<<GRID_H, THREADS>>>((const float4*)x, n4, out, n);
}